// round 11
// baseline (speedup 1.0000x reference)
#include <cuda_runtime.h>
#include <cstdint>

// SAME-padded stride-1 3x3 conv, NHWC fp32, tf32 mma.sync implicit GEMM.
// Round 11: R10 (8 warps x 112x32, halo-A, 2-tap B phases) with
// restructured fragment loads: loop-invariant smem pointers + immediate
// offsets, B fragments preloaded for all 4 j-steps -> far less address ALU.

#define CB    32
#define CH    56
#define CW    56
#define CCIN  128
#define CCOUT 256
#define NPIX  (CB * CH * CW)      // 100352
#define KTOT  1152
#define NPHASES 20                // 4 cin-chunks * 5 phases (2,2,2,2,1 taps)

#define BM 448                    // 8 rows x 56
#define BN 64
#define NTHREADS 256              // 8 warps, 4(M) x 2(N), warp 112x32

#define HR 10                     // halo rows  (8 + 2)
#define HC 58                     // halo cols  (56 + 2)
#define HPIX (HR * HC)            // 580
#define AROW 40                   // words per halo pixel (32 data + 8 pad)
#define BROW 40
#define A_STAGE_W (HPIX * AROW)   // 23200 words (92800 B)
#define B_TAP_W   (BN * BROW)     // 2560 words  (10240 B)
#define B_STAGE_W (2 * B_TAP_W)   // 5120 words  (2 taps)
#define SMEM_BYTES ((2 * A_STAGE_W + 2 * B_STAGE_W) * 4)   // 226560

#define XGROUPS (NPIX * CCIN / 8 / 256)   // 6272 blocks for x-prep

// ---------------- scratch: tf32(rne)-rounded, cin-permuted copies ----------
__device__ __align__(1024) float g_x_t[NPIX * CCIN];    // [pix][cin']
__device__ __align__(1024) float g_w_t[CCOUT * KTOT];   // [cout][k'] transposed

// ---------------- helpers ----------------
__device__ __forceinline__ uint32_t smem_u32(const void* p) {
    uint32_t a;
    asm("{ .reg .u64 t; cvta.to.shared.u64 t, %1; cvt.u32.u64 %0, t; }"
        : "=r"(a) : "l"(p));
    return a;
}

__device__ __forceinline__ void cp16(uint32_t dst, const void* src, uint32_t srcsz) {
    asm volatile("cp.async.cg.shared.global [%0], [%1], 16, %2;"
                 :: "r"(dst), "l"(src), "r"(srcsz) : "memory");
}
#define CP_COMMIT() asm volatile("cp.async.commit_group;" ::: "memory")
#define CP_WAIT0()  asm volatile("cp.async.wait_group 0;" ::: "memory")
#define CP_WAIT1()  asm volatile("cp.async.wait_group 1;" ::: "memory")

__device__ __forceinline__ void mma_tf32(float c[4], const uint32_t a[4],
                                         const uint32_t b[2]) {
    asm volatile(
        "mma.sync.aligned.m16n8k8.row.col.f32.tf32.tf32.f32 "
        "{%0,%1,%2,%3}, {%4,%5,%6,%7}, {%8,%9}, {%0,%1,%2,%3};"
        : "+f"(c[0]), "+f"(c[1]), "+f"(c[2]), "+f"(c[3])
        : "r"(a[0]), "r"(a[1]), "r"(a[2]), "r"(a[3]),
          "r"(b[0]), "r"(b[1]));
}

__device__ __forceinline__ float rna_tf32(float v) {
    uint32_t r;
    asm("cvt.rna.tf32.f32 %0, %1;" : "=r"(r) : "f"(v));
    return __uint_as_float(r);
}

// ---------------- merged pre-kernel ----------------
__global__ void k_prep(const float* __restrict__ x, const float* __restrict__ w,
                       float* __restrict__ gx, float* __restrict__ gw)
{
    const int bid = blockIdx.x;
    if (bid < XGROUPS) {
        const int g = bid * 256 + threadIdx.x;
        const float4* i4 = (const float4*)(x) + g * 2;
        float4 a = i4[0];   // c0..c3
        float4 b = i4[1];   // c4..c7
        float4 o0, o1;
        o0.x = rna_tf32(a.x); o0.y = rna_tf32(b.x);
        o0.z = rna_tf32(a.y); o0.w = rna_tf32(b.y);
        o1.x = rna_tf32(a.z); o1.y = rna_tf32(b.z);
        o1.z = rna_tf32(a.w); o1.w = rna_tf32(b.w);
        float4* o4 = (float4*)(gx) + g * 2;
        o4[0] = o0;
        o4[1] = o1;
    } else {
        const int idx = (bid - XGROUPS) * 256 + threadIdx.x;  // [co][kp]
        const int co = idx / KTOT;
        const int kp = idx % KTOT;
        const int g = kp >> 3, r = kp & 7;
        const int c = (r & 1) ? (4 + (r >> 1)) : (r >> 1);    // inverse perm
        gw[idx] = rna_tf32(w[(size_t)(g * 8 + c) * CCOUT + co]);
    }
}

// ---------------- main kernel ----------------
__global__ __launch_bounds__(NTHREADS, 1)
void conv_mma(const float* __restrict__ xt, const float* __restrict__ wt,
              const float* __restrict__ bias, float* __restrict__ out)
{
    extern __shared__ float smem[];
    const uint32_t sbase = smem_u32(smem);

    const int tid  = threadIdx.x;
    const int wid  = tid >> 5;
    const int lane = tid & 31;
    const int lr   = lane >> 2;    // 0..7
    const int lc   = lane & 3;     // 0..3
    const int bn = blockIdx.x;     // 0..3   (cout block of 64)
    const int n  = blockIdx.y / 7;           // image
    const int h0 = (blockIdx.y % 7) * 8;     // first output row

    const int warp_m = wid >> 1;   // 0..3
    const int warp_n = wid & 1;    // 0..1

    // ---- fragment A base offsets (words, incl. lc*2 k-offset) ----
    int abase[7][2];
    #pragma unroll
    for (int t = 0; t < 7; ++t)
        #pragma unroll
        for (int h = 0; h < 2; ++h) {
            const int m = warp_m * 112 + t * 16 + lr + h * 8;   // 0..447
            const int r = m / 56, c = m % 56;
            abase[t][h] = ((r + 1) * HC + (c + 1)) * AROW + lc * 2;
        }

    const float* xbase = xt + (size_t)(n * (CH * CW)) * CCIN;

    float acc[7][4][4];
    #pragma unroll
    for (int t = 0; t < 7; ++t)
        #pragma unroll
        for (int u = 0; u < 4; ++u)
            #pragma unroll
            for (int r = 0; r < 4; ++r)
                acc[t][u][r] = 0.0f;

    // ---- fill 2 halo rows (rq = 0..4) of A buffer `buf` for `chunk` ----
    auto fill_A_rows = [&](int chunk, int buf, int rq) {
        const uint32_t dst0 = sbase + (uint32_t)buf * (A_STAGE_W * 4);
        for (int idx = tid; idx < 2 * HC * 8; idx += NTHREADS) {
            const int pix = idx >> 3;            // 0..115
            const int seg = idx & 7;
            const int hr = (pix >= HC) ? 1 : 0;  // no division
            const int wc = pix - hr * HC;
            const int h = h0 - 1 + rq * 2 + hr, w2 = wc - 1;
            const bool ok = ((unsigned)h < CH) && ((unsigned)w2 < CW);
            const float* src = xbase
                + (ok ? ((size_t)(h * CW + w2) * CCIN + chunk * 32 + seg * 4) : 0);
            cp16(dst0 + (uint32_t)(rq * 2 * HC + pix) * (AROW * 4) + seg * 16,
                 src, ok ? 16u : 0u);
        }
    };
    // ---- fill B buffer for phase p: ntaps taps starting at t0, chunk ----
    auto fill_B = [&](int p) {
        const int q = p % 5, chunk = p / 5;
        const int t0 = 2 * q;
        const int ntaps = (q == 4) ? 1 : 2;
        const uint32_t dst0 = sbase
            + (uint32_t)(2 * A_STAGE_W + (p & 1) * B_STAGE_W) * 4;
        for (int idx = tid; idx < ntaps * BN * 8; idx += NTHREADS) {
            const int tt  = idx >> 9;         // 0..1
            const int row = (idx >> 3) & 63;
            const int seg = idx & 7;
            const float* src = wt + (size_t)(bn * BN + row) * KTOT
                             + (t0 + tt) * 128 + chunk * 32 + seg * 4;
            cp16(dst0 + (uint32_t)(tt * BN + row) * (BROW * 4) + seg * 16,
                 src, 16u);
        }
    };

    // ---- prologue: A(chunk0) full + B(phase0), one group ----
    #pragma unroll
    for (int rq = 0; rq < 5; ++rq) fill_A_rows(0, 0, rq);
    fill_B(0);
    CP_COMMIT();

    #pragma unroll 1
    for (int p = 0; p < NPHASES; ++p) {
        const int q = p % 5, chunk = p / 5;
        const int t0 = 2 * q;
        const int ntaps = (q == 4) ? 1 : 2;

        if (q == 0) CP_WAIT0();
        else        CP_WAIT1();
        __syncthreads();

        if (p + 1 < NPHASES) fill_B(p + 1);
        CP_COMMIT();
        if (chunk < 3) fill_A_rows(chunk + 1, (chunk + 1) & 1, q);
        CP_COMMIT();

        const float* As = smem + (chunk & 1) * A_STAGE_W;

        #pragma unroll
        for (int tt = 0; tt < 2; ++tt) {
            if (tt < ntaps) {
                const int tap = t0 + tt;
                const int kh = tap / 3, kw = tap - kh * 3;
                const int toff = ((kh - 1) * HC + (kw - 1)) * AROW;

                // ---- B fragments for all 4 j-steps (immediate offsets) ----
                const float* Bs = smem + 2 * A_STAGE_W + (p & 1) * B_STAGE_W
                                + tt * B_TAP_W + (warp_n * 32) * BROW + lc * 2;
                uint32_t b[4][4][2];               // [j][u][2]
                #pragma unroll
                for (int u = 0; u < 4; ++u) {
                    const float* pb = Bs + (u * 8 + lr) * BROW;
                    #pragma unroll
                    for (int j = 0; j < 4; ++j) {
                        const float2 bb = *(const float2*)(pb + j * 8);
                        b[j][u][0] = __float_as_uint(bb.x);
                        b[j][u][1] = __float_as_uint(bb.y);
                    }
                }

                // ---- per m-tile: 8 LDS (imm offsets) then 16 MMAs ----
                const float* At = As + toff;
                #pragma unroll
                for (int t = 0; t < 7; ++t) {
                    const float* p0 = At + abase[t][0];
                    const float* p1 = At + abase[t][1];
                    uint32_t a[4][4];              // [j][4]
                    #pragma unroll
                    for (int j = 0; j < 4; ++j) {
                        const float2 lo = *(const float2*)(p0 + j * 8);
                        const float2 hi = *(const float2*)(p1 + j * 8);
                        a[j][0] = __float_as_uint(lo.x);
                        a[j][1] = __float_as_uint(hi.x);
                        a[j][2] = __float_as_uint(lo.y);
                        a[j][3] = __float_as_uint(hi.y);
                    }
                    #pragma unroll
                    for (int j = 0; j < 4; ++j)
                        #pragma unroll
                        for (int u = 0; u < 4; ++u)
                            mma_tf32(acc[t][u], a[j], b[j][u]);
                }
            }
        }
    }

    // ---------------- epilogue: bias + store ----------------
    const int pixbase = n * (CH * CW) + h0 * CW;
    float bv0[4], bv1[4];
    #pragma unroll
    for (int u = 0; u < 4; ++u) {
        const int c = bn * BN + warp_n * 32 + u * 8 + lc * 2;
        bv0[u] = bias[c];
        bv1[u] = bias[c + 1];
    }
    #pragma unroll
    for (int t = 0; t < 7; ++t) {
        const int m0 = warp_m * 112 + t * 16 + lr;
        #pragma unroll
        for (int u = 0; u < 4; ++u) {
            const int c = bn * BN + warp_n * 32 + u * 8 + lc * 2;
            float2 v0 = make_float2(acc[t][u][0] + bv0[u], acc[t][u][1] + bv1[u]);
            float2 v1 = make_float2(acc[t][u][2] + bv0[u], acc[t][u][3] + bv1[u]);
            *(float2*)(out + (size_t)(pixbase + m0) * CCOUT + c)     = v0;
            *(float2*)(out + (size_t)(pixbase + m0 + 8) * CCOUT + c) = v1;
        }
    }
}

// ---------------- host launch ----------------
extern "C" void kernel_launch(void* const* d_in, const int* in_sizes, int n_in,
                              void* d_out, int out_size)
{
    const float* x    = (const float*)d_in[0];
    const float* w    = (const float*)d_in[1];
    const float* bias = (const float*)d_in[2];
    float* out = (float*)d_out;

    float *gx = nullptr, *gw = nullptr;
    cudaGetSymbolAddress((void**)&gx, g_x_t);
    cudaGetSymbolAddress((void**)&gw, g_w_t);

    // merged pre-pass: tf32(rne) + within-8 cin permutation (+ w transpose)
    k_prep<<<XGROUPS + KTOT * CCOUT / 256, 256>>>(x, w, gx, gw);

    cudaFuncSetAttribute(conv_mma, cudaFuncAttributeMaxDynamicSharedMemorySize,
                         SMEM_BYTES);
    // grid: 4 cout-blocks x (32 images * 7 row-blocks) = 896 CTAs
    dim3 grid(CCOUT / BN, CB * (CH / 8));
    conv_mma<<<grid, NTHREADS, SMEM_BYTES>>>(gx, gw, bias, out);
}

// round 12
// speedup vs baseline: 1.0443x; 1.0443x over previous
#include <cuda_runtime.h>
#include <cstdint>

// SAME-padded stride-1 3x3 conv, NHWC fp32, tf32 mma.sync implicit GEMM.
// Round 12: B operands pre-packed into per-lane fragment order (w_frag) and
// fetched with coalesced LDG.128 -> no B smem, no B barriers; only 4
// chunk-boundary syncs. A: halo tile double buffer (R10).
// CTA = 8 rows x 56 cols of one image (BM=448) x BN=64, 8 warps (112x32).

#define CB    32
#define CH    56
#define CW    56
#define CCIN  128
#define CCOUT 256
#define NPIX  (CB * CH * CW)      // 100352
#define KTOT  1152

#define BM 448                    // 8 rows x 56
#define BN 64
#define NTHREADS 256              // 8 warps, 4(M) x 2(N), warp 112x32

#define HR 10                     // halo rows  (8 + 2)
#define HC 58                     // halo cols  (56 + 2)
#define HPIX (HR * HC)            // 580
#define AROW 40                   // words per halo pixel (32 data + 8 pad)
#define A_STAGE_W (HPIX * AROW)   // 23200 words (92800 B)
#define SMEM_BYTES (2 * A_STAGE_W * 4)   // 185600

#define XGROUPS (NPIX * CCIN / 8 / 256)  // 6272 blocks for x-prep
#define WFRAG_TOTAL (KTOT * CCOUT)       // 294912 floats

// ---------------- scratch ----------------
__device__ __align__(1024) float g_x_t[NPIX * CCIN];     // tf32(rne), cin-permuted
// w_frag: [B0=8][tap=9][chunk=4][u=4][jh=2][lane=32][q=4] floats
// (B0 = 32-cout warp group; q packs {j=jh*2: pair, j=jh*2+1: pair})
__device__ __align__(1024) float g_w_f[WFRAG_TOTAL];

// ---------------- helpers ----------------
__device__ __forceinline__ uint32_t smem_u32(const void* p) {
    uint32_t a;
    asm("{ .reg .u64 t; cvta.to.shared.u64 t, %1; cvt.u32.u64 %0, t; }"
        : "=r"(a) : "l"(p));
    return a;
}

__device__ __forceinline__ void cp16(uint32_t dst, const void* src, uint32_t srcsz) {
    asm volatile("cp.async.cg.shared.global [%0], [%1], 16, %2;"
                 :: "r"(dst), "l"(src), "r"(srcsz) : "memory");
}
#define CP_COMMIT() asm volatile("cp.async.commit_group;" ::: "memory")
#define CP_WAIT0()  asm volatile("cp.async.wait_group 0;" ::: "memory")

__device__ __forceinline__ void mma_tf32(float c[4], const uint32_t a[4],
                                         uint32_t b0, uint32_t b1) {
    asm volatile(
        "mma.sync.aligned.m16n8k8.row.col.f32.tf32.tf32.f32 "
        "{%0,%1,%2,%3}, {%4,%5,%6,%7}, {%8,%9}, {%0,%1,%2,%3};"
        : "+f"(c[0]), "+f"(c[1]), "+f"(c[2]), "+f"(c[3])
        : "r"(a[0]), "r"(a[1]), "r"(a[2]), "r"(a[3]),
          "r"(b0), "r"(b1));
}

__device__ __forceinline__ float rna_tf32(float v) {
    uint32_t r;
    asm("cvt.rna.tf32.f32 %0, %1;" : "=r"(r) : "f"(v));
    return __uint_as_float(r);
}

// ---------------- merged pre-kernel ----------------
// blocks [0, XGROUPS): x — within-8 cin permutation, tf32(rne).
// blocks [XGROUPS, +1152): w -> w_frag per-lane fragment packing, tf32(rne).
__global__ void k_prep(const float* __restrict__ x, const float* __restrict__ w,
                       float* __restrict__ gx, float* __restrict__ gwf)
{
    const int bid = blockIdx.x;
    if (bid < XGROUPS) {
        const int g = bid * 256 + threadIdx.x;
        const float4* i4 = (const float4*)(x) + g * 2;
        float4 a = i4[0];   // c0..c3
        float4 b = i4[1];   // c4..c7
        float4 o0, o1;
        o0.x = rna_tf32(a.x); o0.y = rna_tf32(b.x);
        o0.z = rna_tf32(a.y); o0.w = rna_tf32(b.y);
        o1.x = rna_tf32(a.z); o1.y = rna_tf32(b.z);
        o1.z = rna_tf32(a.w); o1.w = rna_tf32(b.w);
        float4* o4 = (float4*)(gx) + g * 2;
        o4[0] = o0;
        o4[1] = o1;
    } else {
        const int f = (bid - XGROUPS) * 256 + threadIdx.x;  // 0..294911
        const int q     = f & 3;
        const int lane  = (f >> 2) & 31;
        const int jh    = (f >> 7) & 1;
        const int u     = (f >> 8) & 3;
        const int chunk = (f >> 10) & 3;
        const int rem   = f >> 12;          // B0*9 + tap
        const int B0    = rem / 9;
        const int tap   = rem - B0 * 9;
        const int lr = lane >> 2, lc = lane & 3;
        const int j = jh * 2 + (q >> 1);
        const int e = q & 1;
        const int cin  = (chunk * 4 + j) * 8 + lc + e * 4;
        const int cout = B0 * 32 + u * 8 + lr;
        gwf[f] = rna_tf32(w[(size_t)(tap * 128 + cin) * CCOUT + cout]);
    }
}

// ---------------- main kernel ----------------
__global__ __launch_bounds__(NTHREADS, 1)
void conv_mma(const float* __restrict__ xt, const float* __restrict__ wf,
              const float* __restrict__ bias, float* __restrict__ out)
{
    extern __shared__ float smem[];
    const uint32_t sbase = smem_u32(smem);

    const int tid  = threadIdx.x;
    const int wid  = tid >> 5;
    const int lane = tid & 31;
    const int lr   = lane >> 2;    // 0..7
    const int lc   = lane & 3;     // 0..3
    const int bn = blockIdx.x;     // 0..3   (cout block of 64)
    const int n  = blockIdx.y / 7;           // image
    const int h0 = (blockIdx.y % 7) * 8;     // first output row

    const int warp_m = wid >> 1;   // 0..3
    const int warp_n = wid & 1;    // 0..1

    // ---- fragment A base offsets (words, incl. lc*2 k-offset) ----
    int abase[7][2];
    #pragma unroll
    for (int t = 0; t < 7; ++t)
        #pragma unroll
        for (int h = 0; h < 2; ++h) {
            const int m = warp_m * 112 + t * 16 + lr + h * 8;   // 0..447
            const int r = m / 56, c = m % 56;
            abase[t][h] = ((r + 1) * HC + (c + 1)) * AROW + lc * 2;
        }

    const float* xbase = xt + (size_t)(n * (CH * CW)) * CCIN;
    // per-warp w_frag base (float4 units), lane folded in
    const float4* wf4 = (const float4*)(wf)
                      + (size_t)(bn * 2 + warp_n) * (36 * 256) + lane;

    float acc[7][4][4];
    #pragma unroll
    for (int t = 0; t < 7; ++t)
        #pragma unroll
        for (int u = 0; u < 4; ++u)
            #pragma unroll
            for (int r = 0; r < 4; ++r)
                acc[t][u][r] = 0.0f;

    // ---- fill 2 halo rows (rq = 0..4) of A buffer `buf` for `chunk` ----
    auto fill_A_rows = [&](int chunk, int buf, int rq) {
        const uint32_t dst0 = sbase + (uint32_t)buf * (A_STAGE_W * 4);
        for (int idx = tid; idx < 2 * HC * 8; idx += NTHREADS) {
            const int pix = idx >> 3;            // 0..115
            const int seg = idx & 7;
            const int hr = (pix >= HC) ? 1 : 0;
            const int wc = pix - hr * HC;
            const int h = h0 - 1 + rq * 2 + hr, w2 = wc - 1;
            const bool ok = ((unsigned)h < CH) && ((unsigned)w2 < CW);
            const float* src = xbase
                + (ok ? ((size_t)(h * CW + w2) * CCIN + chunk * 32 + seg * 4) : 0);
            cp16(dst0 + (uint32_t)(rq * 2 * HC + pix) * (AROW * 4) + seg * 16,
                 src, ok ? 16u : 0u);
        }
    };

    // ---- prologue: A(chunk0) ----
    #pragma unroll
    for (int rq = 0; rq < 5; ++rq) fill_A_rows(0, 0, rq);
    CP_COMMIT();

    #pragma unroll 1
    for (int chunk = 0; chunk < 4; ++chunk) {
        CP_WAIT0();           // A(chunk) resident
        __syncthreads();      // safe to overwrite the other buffer / use this one

        const float* As = smem + (chunk & 1) * A_STAGE_W;

        #pragma unroll 1
        for (int tap = 0; tap < 9; ++tap) {
            // refill other A buffer for next chunk during taps 2..6
            if (chunk < 3 && tap >= 2 && tap <= 6) {
                fill_A_rows(chunk + 1, (chunk + 1) & 1, tap - 2);
                CP_COMMIT();
            }

            // ---- B fragments: 8 coalesced LDG.128 ----
            const float4* wt4 = wf4 + (tap * 4 + chunk) * 256;
            float4 bx[8];
            #pragma unroll
            for (int ui = 0; ui < 8; ++ui)
                bx[ui] = wt4[ui * 32];

            // b[j][u] pairs from packed float4s
            uint32_t b[4][4][2];
            #pragma unroll
            for (int u = 0; u < 4; ++u) {
                b[0][u][0] = __float_as_uint(bx[u * 2 + 0].x);
                b[0][u][1] = __float_as_uint(bx[u * 2 + 0].y);
                b[1][u][0] = __float_as_uint(bx[u * 2 + 0].z);
                b[1][u][1] = __float_as_uint(bx[u * 2 + 0].w);
                b[2][u][0] = __float_as_uint(bx[u * 2 + 1].x);
                b[2][u][1] = __float_as_uint(bx[u * 2 + 1].y);
                b[3][u][0] = __float_as_uint(bx[u * 2 + 1].z);
                b[3][u][1] = __float_as_uint(bx[u * 2 + 1].w);
            }

            const int kh = tap / 3, kw = tap - kh * 3;
            const float* At = As + ((kh - 1) * HC + (kw - 1)) * AROW;

            #pragma unroll
            for (int t = 0; t < 7; ++t) {
                const float* p0 = At + abase[t][0];
                const float* p1 = At + abase[t][1];
                uint32_t a[4][4];              // [j][4]
                #pragma unroll
                for (int j = 0; j < 4; ++j) {
                    const float2 lo = *(const float2*)(p0 + j * 8);
                    const float2 hi = *(const float2*)(p1 + j * 8);
                    a[j][0] = __float_as_uint(lo.x);
                    a[j][1] = __float_as_uint(hi.x);
                    a[j][2] = __float_as_uint(lo.y);
                    a[j][3] = __float_as_uint(hi.y);
                }
                #pragma unroll
                for (int j = 0; j < 4; ++j)
                    #pragma unroll
                    for (int u = 0; u < 4; ++u)
                        mma_tf32(acc[t][u], a[j], b[j][u][0], b[j][u][1]);
            }
        }
    }

    // ---------------- epilogue: bias + store ----------------
    const int pixbase = n * (CH * CW) + h0 * CW;
    float bv0[4], bv1[4];
    #pragma unroll
    for (int u = 0; u < 4; ++u) {
        const int c = bn * BN + warp_n * 32 + u * 8 + lc * 2;
        bv0[u] = bias[c];
        bv1[u] = bias[c + 1];
    }
    #pragma unroll
    for (int t = 0; t < 7; ++t) {
        const int m0 = warp_m * 112 + t * 16 + lr;
        #pragma unroll
        for (int u = 0; u < 4; ++u) {
            const int c = bn * BN + warp_n * 32 + u * 8 + lc * 2;
            float2 v0 = make_float2(acc[t][u][0] + bv0[u], acc[t][u][1] + bv1[u]);
            float2 v1 = make_float2(acc[t][u][2] + bv0[u], acc[t][u][3] + bv1[u]);
            *(float2*)(out + (size_t)(pixbase + m0) * CCOUT + c)     = v0;
            *(float2*)(out + (size_t)(pixbase + m0 + 8) * CCOUT + c) = v1;
        }
    }
}

// ---------------- host launch ----------------
extern "C" void kernel_launch(void* const* d_in, const int* in_sizes, int n_in,
                              void* d_out, int out_size)
{
    const float* x    = (const float*)d_in[0];
    const float* w    = (const float*)d_in[1];
    const float* bias = (const float*)d_in[2];
    float* out = (float*)d_out;

    float *gx = nullptr, *gwf = nullptr;
    cudaGetSymbolAddress((void**)&gx, g_x_t);
    cudaGetSymbolAddress((void**)&gwf, g_w_f);

    // merged pre-pass: x tf32+permute, w -> per-lane fragment pack
    k_prep<<<XGROUPS + WFRAG_TOTAL / 256, 256>>>(x, w, gx, gwf);

    cudaFuncSetAttribute(conv_mma, cudaFuncAttributeMaxDynamicSharedMemorySize,
                         SMEM_BYTES);
    // grid: 4 cout-blocks x (32 images * 7 row-blocks) = 896 CTAs
    dim3 grid(CCOUT / BN, CB * (CH / 8));
    conv_mma<<<grid, NTHREADS, SMEM_BYTES>>>(gx, gwf, bias, out);
}